// round 15
// baseline (speedup 1.0000x reference)
#include <cuda_runtime.h>
#include <cuda_fp16.h>
#include <cstdint>

#define BSZ 4
#define SEQ 2048
#define EMB 1024
#define NH  16
#define HD  64
#define MTOT (BSZ*SEQ)       /* 8192 */
#define NQKV (3*EMB)         /* 3072 */
#define NEG_BIG (-3.0e38f)
#define LOG2E 1.4426950408889634f

// Scratch (device globals: allocation-free per harness rules)
__device__ __half g_xh [(size_t)MTOT*EMB];        // x in fp16
__device__ __half g_wh [(size_t)EMB*NQKV];        // w_qkv in fp16
__device__ __half g_wph[(size_t)EMB*EMB];         // w_proj in fp16
__device__ __half g_q[(size_t)BSZ*NH*SEQ*HD];     // [B,H,S,D] fp16
__device__ __half g_k[(size_t)BSZ*NH*SEQ*HD];
__device__ __half g_v[(size_t)BSZ*NH*SEQ*HD];
__device__ __half g_y[(size_t)MTOT*EMB];          // attn out [B*S,E] fp16

// ---------------------------------------------------------------------------
// Helpers
// ---------------------------------------------------------------------------
__device__ __forceinline__ float ex2(float x) {
    float r;
    asm("ex2.approx.ftz.f32 %0, %1;" : "=f"(r) : "f"(x));
    return r;
}
__device__ __forceinline__ uint32_t smem_u32(const void* p) {
    uint32_t a;
    asm("{ .reg .u64 t; cvta.to.shared.u64 t, %1; cvt.u32.u64 %0, t; }"
        : "=r"(a) : "l"(p));
    return a;
}
__device__ __forceinline__ uint32_t packh2(float x, float y) {
    __half2 h = __floats2half2_rn(x, y);
    return *(uint32_t*)&h;
}

#define CPA16(dst, src) \
    asm volatile("cp.async.cg.shared.global [%0], [%1], 16;" \
                 :: "r"(dst), "l"(src))
#define CP_COMMIT() asm volatile("cp.async.commit_group;" ::: "memory")
#define CP_WAIT0()  asm volatile("cp.async.wait_group 0;" ::: "memory")
#define CP_WAIT1()  asm volatile("cp.async.wait_group 1;" ::: "memory")

#define LDSM4(r0,r1,r2,r3,addr) \
    asm volatile("ldmatrix.sync.aligned.m8n8.x4.shared.b16 {%0,%1,%2,%3}, [%4];" \
        : "=r"(r0),"=r"(r1),"=r"(r2),"=r"(r3) : "r"(addr))
#define LDSM4T(r0,r1,r2,r3,addr) \
    asm volatile("ldmatrix.sync.aligned.m8n8.x4.trans.shared.b16 {%0,%1,%2,%3}, [%4];" \
        : "=r"(r0),"=r"(r1),"=r"(r2),"=r"(r3) : "r"(addr))

// D += A(16x16) * B(16x8), fp16 in, fp32 accum
__device__ __forceinline__ void mma16(float* c, const uint32_t* a,
                                      uint32_t b0, uint32_t b1) {
    asm volatile(
        "mma.sync.aligned.m16n8k16.row.col.f32.f16.f16.f32 "
        "{%0,%1,%2,%3}, {%4,%5,%6,%7}, {%8,%9}, {%0,%1,%2,%3};"
        : "+f"(c[0]), "+f"(c[1]), "+f"(c[2]), "+f"(c[3])
        : "r"(a[0]), "r"(a[1]), "r"(a[2]), "r"(a[3]), "r"(b0), "r"(b1));
}

// ---------------------------------------------------------------------------
// fp32 -> fp16 convert (all three tensors, one launch, 8 elems/thread)
// ---------------------------------------------------------------------------
#define N8_X  (MTOT*EMB/8)
#define N8_WQ (EMB*NQKV/8)
#define N8_WP (EMB*EMB/8)
__global__ __launch_bounds__(256) void cvt_all_kernel(
    const float* __restrict__ x, const float* __restrict__ wq,
    const float* __restrict__ wp)
{
    const int i = blockIdx.x * 256 + threadIdx.x;
    const float* src; __half* dst; size_t off;
    if (i < N8_X)                { src = x;  dst = g_xh;  off = i; }
    else if (i < N8_X + N8_WQ)   { src = wq; dst = g_wh;  off = i - N8_X; }
    else if (i < N8_X + N8_WQ + N8_WP) { src = wp; dst = g_wph; off = i - N8_X - N8_WQ; }
    else return;
    const float4* s = (const float4*)src + off * 2;
    float4 a = s[0], b = s[1];
    __half2 h[4];
    h[0] = __floats2half2_rn(a.x, a.y);
    h[1] = __floats2half2_rn(a.z, a.w);
    h[2] = __floats2half2_rn(b.x, b.y);
    h[3] = __floats2half2_rn(b.z, b.w);
    *(uint4*)(dst + off * 8) = *(uint4*)h;
}

// ---------------------------------------------------------------------------
// Persistent fp16 GEMM: CTA tile 128x128, 128 threads, 4 warps (2m x 2n),
// warp 64x64, BK=64, 3-stage cp.async ring that NEVER drains across tiles:
// fills run 2 chunks ahead in a single global chunk sequence, so a tile's
// last iterations prefetch the next tile's first chunks and the epilogue
// overlaps them. Grid = 2 CTAs/SM, persistent loop over tiles.
// ---------------------------------------------------------------------------
#define G_ABYTES (128*144)              /* 18432 */
#define G_BBYTES (64*272)               /* 17408 */
#define G_STAGE  (G_ABYTES + G_BBYTES)  /* 35840 */
#define G_SMEM   (3*G_STAGE)            /* 107520 */
#define G_KIT    (EMB/64)               /* 16 */
#define PGRID    304                    /* 2 x 152 SMs */
#define QKV_NX   (NQKV/128)             /* 24 */
#define QKV_NT   (QKV_NX * (MTOT/128))  /* 1536 */
#define PROJ_NX  (EMB/128)              /* 8 */
#define PROJ_NT  (PROJ_NX * (MTOT/128)) /* 512 */

template<int LDW, int NX>
__device__ __forceinline__ void p_fill(
    const __half* __restrict__ A, const __half* __restrict__ W,
    int tile, int chunk, uint32_t sbase, int st)
{
    const int tid = threadIdx.x;
    const int bm = (tile / NX) * 128;
    const int bn = (tile % NX) * 128;
    const int kc = chunk * 64;
    const uint32_t as = sbase + st*G_STAGE;
    const uint32_t bs = as + G_ABYTES;
#pragma unroll
    for (int it = 0; it < 8; it++) {  // A: 128 rows x 8 segs (128B/row)
        const int u = it*128 + tid;
        const int r = u >> 3, sg = u & 7;
        CPA16(as + r*144 + sg*16, A + (size_t)(bm + r)*EMB + kc + sg*8);
    }
#pragma unroll
    for (int it = 0; it < 8; it++) {  // B: 64 k-rows x 16 segs (256B/row)
        const int u = it*128 + tid;
        const int k = u >> 4, sg = u & 15;
        CPA16(bs + k*272 + sg*16, W + (size_t)(kc + k)*LDW + bn + sg*8);
    }
}

__device__ __forceinline__ void p_compute_chunk(
    uint32_t sbase, int st, float acc[4][8][4],
    int wm, int wn, int l7, int l8, int l16)
{
    const uint32_t as = sbase + st*G_STAGE;
    const uint32_t bs = as + G_ABYTES;
#pragma unroll
    for (int ks = 0; ks < 4; ks++) {
        uint32_t a[4][4];
#pragma unroll
        for (int mt = 0; mt < 4; mt++) {
            const int row = wm*64 + mt*16 + l7 + l8*8;
            const int col = ks*16 + l16*8;
            LDSM4(a[mt][0], a[mt][1], a[mt][2], a[mt][3],
                  as + row*144 + col*2);
        }
        uint32_t b[8][2];
#pragma unroll
        for (int np = 0; np < 4; np++) {
            const int row = ks*16 + l7 + l16*8;       // k
            const int col = wn*64 + np*16 + l8*8;     // n
            uint32_t r0, r1, r2, r3;
            LDSM4T(r0, r1, r2, r3, bs + row*272 + col*2);
            b[np*2  ][0] = r0; b[np*2  ][1] = r2;
            b[np*2+1][0] = r1; b[np*2+1][1] = r3;
        }
#pragma unroll
        for (int mt = 0; mt < 4; mt++)
#pragma unroll
            for (int nt = 0; nt < 8; nt++)
                mma16(acc[mt][nt], a[mt], b[nt][0], b[nt][1]);
    }
}

// ---------------------------------------------------------------------------
// QKV GEMM (persistent): g_xh @ g_wh + b -> g_q/g_k/g_v (fp16)
// ---------------------------------------------------------------------------
__global__ __launch_bounds__(128, 2) void qkv_gemm_kernel(
    const float* __restrict__ bias)
{
    extern __shared__ char smem[];
    const uint32_t sbase = smem_u32(smem);
    const int warp = threadIdx.x >> 5, lane = threadIdx.x & 31;
    const int wm = warp >> 1, wn = warp & 1;
    const int l7 = lane & 7, l8 = (lane >> 3) & 1, l16 = lane >> 4;
    const int g = lane >> 2, t4 = lane & 3;

    int ft = blockIdx.x, fc = 0;
    p_fill<NQKV, QKV_NX>(g_xh, g_wh, ft, 0, sbase, 0); CP_COMMIT();
    p_fill<NQKV, QKV_NX>(g_xh, g_wh, ft, 1, sbase, 1); CP_COMMIT();
    fc = 2;
    int st = 0;

    for (int t = blockIdx.x; t < QKV_NT; t += PGRID) {
        float acc[4][8][4];
#pragma unroll
        for (int mt = 0; mt < 4; mt++)
#pragma unroll
            for (int nt = 0; nt < 8; nt++)
#pragma unroll
                for (int r = 0; r < 4; r++) acc[mt][nt][r] = 0.f;

        for (int i = 0; i < G_KIT; i++) {
            if (ft >= QKV_NT) CP_WAIT0(); else CP_WAIT1();
            __syncthreads();
            if (ft < QKV_NT) {
                int st2 = st + 2; if (st2 >= 3) st2 -= 3;
                p_fill<NQKV, QKV_NX>(g_xh, g_wh, ft, fc, sbase, st2);
                CP_COMMIT();
                if (++fc == G_KIT) { fc = 0; ft += PGRID; }
            }
            p_compute_chunk(sbase, st, acc, wm, wn, l7, l8, l16);
            if (++st >= 3) st = 0;
        }

        // epilogue (regs -> gmem; overlaps next tile's in-flight fills)
        const int bm = (t / QKV_NX) * 128, bn = (t % QKV_NX) * 128;
#pragma unroll
        for (int mt = 0; mt < 4; mt++) {
#pragma unroll
            for (int nt = 0; nt < 8; nt++) {
                const int n0 = bn + wn*64 + nt*8 + 2*t4;
                const int sect = n0 >> 10;
                const int e = n0 & (EMB-1);
                const int h = e >> 6, d = e & 63;
                __half* dst = (sect == 0) ? g_q : (sect == 1) ? g_k : g_v;
                const float bx = bias[n0], by = bias[n0+1];
#pragma unroll
                for (int half = 0; half < 2; half++) {
                    const int m = bm + wm*64 + mt*16 + g + half*8;
                    const int bb = m >> 11, s = m & (SEQ-1);
                    __half2 v = __floats2half2_rn(acc[mt][nt][half*2+0] + bx,
                                                  acc[mt][nt][half*2+1] + by);
                    *(__half2*)&dst[(((size_t)(bb*NH + h))*SEQ + s)*HD + d] = v;
                }
            }
        }
    }
}

// ---------------------------------------------------------------------------
// Proj GEMM (persistent): g_y @ g_wph + b -> out (fp32)
// ---------------------------------------------------------------------------
__global__ __launch_bounds__(128, 2) void proj_gemm_kernel(
    const float* __restrict__ bias, float* __restrict__ out)
{
    extern __shared__ char smem[];
    const uint32_t sbase = smem_u32(smem);
    const int warp = threadIdx.x >> 5, lane = threadIdx.x & 31;
    const int wm = warp >> 1, wn = warp & 1;
    const int l7 = lane & 7, l8 = (lane >> 3) & 1, l16 = lane >> 4;
    const int g = lane >> 2, t4 = lane & 3;

    int ft = blockIdx.x, fc = 0;
    if (ft < PROJ_NT) {
        p_fill<EMB, PROJ_NX>(g_y, g_wph, ft, 0, sbase, 0); CP_COMMIT();
        p_fill<EMB, PROJ_NX>(g_y, g_wph, ft, 1, sbase, 1); CP_COMMIT();
        fc = 2;
    }
    int st = 0;

    for (int t = blockIdx.x; t < PROJ_NT; t += PGRID) {
        float acc[4][8][4];
#pragma unroll
        for (int mt = 0; mt < 4; mt++)
#pragma unroll
            for (int nt = 0; nt < 8; nt++)
#pragma unroll
                for (int r = 0; r < 4; r++) acc[mt][nt][r] = 0.f;

        for (int i = 0; i < G_KIT; i++) {
            if (ft >= PROJ_NT) CP_WAIT0(); else CP_WAIT1();
            __syncthreads();
            if (ft < PROJ_NT) {
                int st2 = st + 2; if (st2 >= 3) st2 -= 3;
                p_fill<EMB, PROJ_NX>(g_y, g_wph, ft, fc, sbase, st2);
                CP_COMMIT();
                if (++fc == G_KIT) { fc = 0; ft += PGRID; }
            }
            p_compute_chunk(sbase, st, acc, wm, wn, l7, l8, l16);
            if (++st >= 3) st = 0;
        }

        const int bm = (t / PROJ_NX) * 128, bn = (t % PROJ_NX) * 128;
#pragma unroll
        for (int mt = 0; mt < 4; mt++) {
#pragma unroll
            for (int nt = 0; nt < 8; nt++) {
                const int n0 = bn + wn*64 + nt*8 + 2*t4;
                const float bx = bias[n0], by = bias[n0+1];
#pragma unroll
                for (int half = 0; half < 2; half++) {
                    const int m = bm + wm*64 + mt*16 + g + half*8;
                    float2 v;
                    v.x = acc[mt][nt][half*2+0] + bx;
                    v.y = acc[mt][nt][half*2+1] + by;
                    *(float2*)&out[(size_t)m*EMB + n0] = v;
                }
            }
        }
    }
}

// ---------------------------------------------------------------------------
// Flash attention: 128-thread CTA over 64 q-rows (4 warps x 16 rows),
// KV tiles of 64, 3-stage cp.async KV ring, max-free softmax, and
// register P-reuse (S C-fragment repacked directly into PV A-fragment).
// smem (halfs): SQ[64][72] @0; stage s: K @4608+s*9216, V = K+4608.
// Total 64512 B -> 3 CTAs/SM.   (unchanged from round 14, passed)
// ---------------------------------------------------------------------------
#define AQ_OFF  0
#define AKV(s)  (4608 + (s)*9216)
#define ATTN_SMEM_BYTES (32256*2)       /* 64512 */

__global__ __launch_bounds__(128, 3) void attn_kernel()
{
    extern __shared__ __half smh[];
    const uint32_t su = smem_u32(smh);

    const int tid = threadIdx.x;
    const int w = tid >> 5, lane = tid & 31;
    const int g = lane >> 2, t4 = lane & 3;
    const int l7 = lane & 7, l8 = (lane >> 3) & 1, l16 = lane >> 4;
    const int qt = blockIdx.x, bh = blockIdx.y;
    const int q0 = qt * 64;
    const int qrow = w * 16;
    const size_t base = (size_t)bh * SEQ * HD;
    const __half* Qg = g_q + base;
    const __half* Kg = g_k + base;
    const __half* Vg = g_v + base;
    const int ntiles = qt + 1;

    // Q fill (raw copy): 64 rows x 8 segs = 512 units
#pragma unroll
    for (int it = 0; it < 4; it++) {
        const int u = it*128 + tid;
        const int r = u >> 3, sg = u & 7;
        CPA16(su + (AQ_OFF + r*72)*2 + sg*16, Qg + (size_t)(q0 + r)*HD + sg*8);
    }
    // KV tile 0 into stage 0 (same group as Q)
    {
        const uint32_t ak = su + AKV(0)*2, av = ak + 4608*2;
#pragma unroll
        for (int it = 0; it < 4; it++) {
            const int u = it*128 + tid;
            const int r = u >> 3, sg = u & 7;
            CPA16(ak + r*144 + sg*16, Kg + (size_t)r*HD + sg*8);
            CPA16(av + r*144 + sg*16, Vg + (size_t)r*HD + sg*8);
        }
    }
    CP_COMMIT();
    if (ntiles > 1) {
        const uint32_t ak = su + AKV(1)*2, av = ak + 4608*2;
#pragma unroll
        for (int it = 0; it < 4; it++) {
            const int u = it*128 + tid;
            const int r = u >> 3, sg = u & 7;
            CPA16(ak + r*144 + sg*16, Kg + (size_t)(64 + r)*HD + sg*8);
            CPA16(av + r*144 + sg*16, Vg + (size_t)(64 + r)*HD + sg*8);
        }
        CP_COMMIT();
    }

    float l0 = 0.f, l1 = 0.f;
    float oacc[8][4];
#pragma unroll
    for (int nt = 0; nt < 8; nt++)
#pragma unroll
        for (int r = 0; r < 4; r++) oacc[nt][r] = 0.f;

    const float qs2 = 0.125f * LOG2E;
    int st = 0;
    for (int tk = 0; tk < ntiles; tk++) {
        if (tk == ntiles - 1) CP_WAIT0(); else CP_WAIT1();
        __syncthreads();
        if (tk + 2 < ntiles) {
            int st2 = st + 2; if (st2 >= 3) st2 -= 3;
            const uint32_t ak = su + AKV(st2)*2, av = ak + 4608*2;
#pragma unroll
            for (int it = 0; it < 4; it++) {
                const int u = it*128 + tid;
                const int r = u >> 3, sg = u & 7;
                CPA16(ak + r*144 + sg*16, Kg + (size_t)((tk+2)*64 + r)*HD + sg*8);
                CPA16(av + r*144 + sg*16, Vg + (size_t)((tk+2)*64 + r)*HD + sg*8);
            }
            CP_COMMIT();
        }
        const uint32_t ak = su + AKV(st)*2, av = ak + 4608*2;

        // S = Q K^T
        float sacc[8][4];
#pragma unroll
        for (int nt = 0; nt < 8; nt++)
#pragma unroll
            for (int r = 0; r < 4; r++) sacc[nt][r] = 0.f;

#pragma unroll
        for (int ks = 0; ks < 4; ks++) {
            uint32_t a[4];
            {
                const int row = qrow + l7 + l8*8;
                const int col = ks*16 + l16*8;
                LDSM4(a[0], a[1], a[2], a[3], su + (AQ_OFF + row*72 + col)*2);
            }
#pragma unroll
            for (int np = 0; np < 4; np++) {
                const int row = np*16 + l7 + l8*8;
                const int col = ks*16 + l16*8;
                uint32_t r0, r1, r2, r3;
                LDSM4(r0, r1, r2, r3, ak + row*144 + col*2);
                mma16(sacc[np*2],   a, r0, r2);
                mma16(sacc[np*2+1], a, r1, r3);
            }
        }

        const int row0 = q0 + qrow + g;
        const int row1 = row0 + 8;
        if (tk == ntiles - 1) {    // diagonal tile: causal mask
#pragma unroll
            for (int nt = 0; nt < 8; nt++) {
                const int col = tk*64 + nt*8 + 2*t4;
                if (col   > row0) sacc[nt][0] = NEG_BIG;
                if (col+1 > row0) sacc[nt][1] = NEG_BIG;
                if (col   > row1) sacc[nt][2] = NEG_BIG;
                if (col+1 > row1) sacc[nt][3] = NEG_BIG;
            }
        }

        // max-free softmax: p = ex2(s * qs2)  (masked -> ex2(-big) = 0)
        float s0 = 0.f, s1 = 0.f;
#pragma unroll
        for (int nt = 0; nt < 8; nt++) {
            sacc[nt][0] = ex2(sacc[nt][0] * qs2);
            sacc[nt][1] = ex2(sacc[nt][1] * qs2);
            sacc[nt][2] = ex2(sacc[nt][2] * qs2);
            sacc[nt][3] = ex2(sacc[nt][3] * qs2);
            s0 += sacc[nt][0] + sacc[nt][1];
            s1 += sacc[nt][2] + sacc[nt][3];
        }
        s0 += __shfl_xor_sync(0xffffffffu, s0, 1);
        s0 += __shfl_xor_sync(0xffffffffu, s0, 2);
        s1 += __shfl_xor_sync(0xffffffffu, s1, 1);
        s1 += __shfl_xor_sync(0xffffffffu, s1, 2);
        l0 += s0;
        l1 += s1;

        // O += P V  — A-fragment built directly from the S C-fragment
#pragma unroll
        for (int kk = 0; kk < 4; kk++) {
            uint32_t a[4];
            a[0] = packh2(sacc[2*kk  ][0], sacc[2*kk  ][1]);
            a[1] = packh2(sacc[2*kk  ][2], sacc[2*kk  ][3]);
            a[2] = packh2(sacc[2*kk+1][0], sacc[2*kk+1][1]);
            a[3] = packh2(sacc[2*kk+1][2], sacc[2*kk+1][3]);
#pragma unroll
            for (int dp = 0; dp < 4; dp++) {
                const int row = kk*16 + l7 + l16*8;
                const int col = dp*16 + l8*8;
                uint32_t r0, r1, r2, r3;
                LDSM4T(r0, r1, r2, r3, av + row*144 + col*2);
                mma16(oacc[dp*2],   a, r0, r2);
                mma16(oacc[dp*2+1], a, r1, r3);
            }
        }
        if (++st >= 3) st = 0;
    }

    // normalize + write merged-head layout [B*S, E] fp16
    const int b = bh >> 4, h = bh & 15;
    const float i0 = 1.0f / l0, i1 = 1.0f / l1;
    const int r0 = q0 + qrow + g;
#pragma unroll
    for (int nt = 0; nt < 8; nt++) {
        const int col = h*64 + nt*8 + 2*t4;
        *(__half2*)&g_y[((size_t)(b*SEQ + r0))*EMB + col] =
            __floats2half2_rn(oacc[nt][0]*i0, oacc[nt][1]*i0);
        *(__half2*)&g_y[((size_t)(b*SEQ + r0 + 8))*EMB + col] =
            __floats2half2_rn(oacc[nt][2]*i1, oacc[nt][3]*i1);
    }
}

// ---------------------------------------------------------------------------
extern "C" void kernel_launch(void* const* d_in, const int* in_sizes, int n_in,
                              void* d_out, int out_size)
{
    const float* x      = (const float*)d_in[0];
    const float* w_qkv  = (const float*)d_in[1];
    const float* b_qkv  = (const float*)d_in[2];
    const float* w_proj = (const float*)d_in[3];
    const float* b_proj = (const float*)d_in[4];
    float* out = (float*)d_out;

    cudaFuncSetAttribute(qkv_gemm_kernel,
                         cudaFuncAttributeMaxDynamicSharedMemorySize, G_SMEM);
    cudaFuncSetAttribute(proj_gemm_kernel,
                         cudaFuncAttributeMaxDynamicSharedMemorySize, G_SMEM);
    cudaFuncSetAttribute(attn_kernel,
                         cudaFuncAttributeMaxDynamicSharedMemorySize, ATTN_SMEM_BYTES);

    const int ncvt = N8_X + N8_WQ + N8_WP;
    cvt_all_kernel<<<(ncvt + 255)/256, 256>>>(x, w_qkv, w_proj);

    qkv_gemm_kernel<<<PGRID, 128, G_SMEM>>>(b_qkv);
    attn_kernel<<<dim3(SEQ/64, BSZ*NH), 128, ATTN_SMEM_BYTES>>>();
    proj_gemm_kernel<<<PGRID, 128, G_SMEM>>>(b_proj, out);
}

// round 16
// speedup vs baseline: 1.0401x; 1.0401x over previous
#include <cuda_runtime.h>
#include <cuda_fp16.h>
#include <cstdint>

#define BSZ 4
#define SEQ 2048
#define EMB 1024
#define NH  16
#define HD  64
#define MTOT (BSZ*SEQ)       /* 8192 */
#define NQKV (3*EMB)         /* 3072 */
#define NEG_BIG (-3.0e38f)
#define LOG2E 1.4426950408889634f

// Scratch (device globals: allocation-free per harness rules)
__device__ __half g_xh [(size_t)MTOT*EMB];        // x in fp16
__device__ __half g_wh [(size_t)EMB*NQKV];        // w_qkv in fp16
__device__ __half g_wph[(size_t)EMB*EMB];         // w_proj in fp16
__device__ __half g_q[(size_t)BSZ*NH*SEQ*HD];     // [B,H,S,D] fp16
__device__ __half g_k[(size_t)BSZ*NH*SEQ*HD];
__device__ __half g_v[(size_t)BSZ*NH*SEQ*HD];
__device__ __half g_y[(size_t)MTOT*EMB];          // attn out [B*S,E] fp16

// ---------------------------------------------------------------------------
// Helpers
// ---------------------------------------------------------------------------
__device__ __forceinline__ float ex2(float x) {
    float r;
    asm("ex2.approx.ftz.f32 %0, %1;" : "=f"(r) : "f"(x));
    return r;
}
__device__ __forceinline__ uint32_t smem_u32(const void* p) {
    uint32_t a;
    asm("{ .reg .u64 t; cvta.to.shared.u64 t, %1; cvt.u32.u64 %0, t; }"
        : "=r"(a) : "l"(p));
    return a;
}
__device__ __forceinline__ uint32_t packh2(float x, float y) {
    __half2 h = __floats2half2_rn(x, y);
    return *(uint32_t*)&h;
}

#define CPA16(dst, src) \
    asm volatile("cp.async.cg.shared.global [%0], [%1], 16;" \
                 :: "r"(dst), "l"(src))
#define CP_COMMIT() asm volatile("cp.async.commit_group;" ::: "memory")
#define CP_WAIT0()  asm volatile("cp.async.wait_group 0;" ::: "memory")
#define CP_WAIT1()  asm volatile("cp.async.wait_group 1;" ::: "memory")

#define LDSM4(r0,r1,r2,r3,addr) \
    asm volatile("ldmatrix.sync.aligned.m8n8.x4.shared.b16 {%0,%1,%2,%3}, [%4];" \
        : "=r"(r0),"=r"(r1),"=r"(r2),"=r"(r3) : "r"(addr))
#define LDSM4T(r0,r1,r2,r3,addr) \
    asm volatile("ldmatrix.sync.aligned.m8n8.x4.trans.shared.b16 {%0,%1,%2,%3}, [%4];" \
        : "=r"(r0),"=r"(r1),"=r"(r2),"=r"(r3) : "r"(addr))

// D += A(16x16) * B(16x8), fp16 in, fp32 accum
__device__ __forceinline__ void mma16(float* c, const uint32_t* a,
                                      uint32_t b0, uint32_t b1) {
    asm volatile(
        "mma.sync.aligned.m16n8k16.row.col.f32.f16.f16.f32 "
        "{%0,%1,%2,%3}, {%4,%5,%6,%7}, {%8,%9}, {%0,%1,%2,%3};"
        : "+f"(c[0]), "+f"(c[1]), "+f"(c[2]), "+f"(c[3])
        : "r"(a[0]), "r"(a[1]), "r"(a[2]), "r"(a[3]), "r"(b0), "r"(b1));
}

// ---------------------------------------------------------------------------
// fp32 -> fp16 convert (all three tensors, one launch, 8 elems/thread)
// ---------------------------------------------------------------------------
#define N8_X  (MTOT*EMB/8)
#define N8_WQ (EMB*NQKV/8)
#define N8_WP (EMB*EMB/8)
__global__ __launch_bounds__(256) void cvt_all_kernel(
    const float* __restrict__ x, const float* __restrict__ wq,
    const float* __restrict__ wp)
{
    const int i = blockIdx.x * 256 + threadIdx.x;
    const float* src; __half* dst; size_t off;
    if (i < N8_X)                { src = x;  dst = g_xh;  off = i; }
    else if (i < N8_X + N8_WQ)   { src = wq; dst = g_wh;  off = i - N8_X; }
    else if (i < N8_X + N8_WQ + N8_WP) { src = wp; dst = g_wph; off = i - N8_X - N8_WQ; }
    else return;
    const float4* s = (const float4*)src + off * 2;
    float4 a = s[0], b = s[1];
    __half2 h[4];
    h[0] = __floats2half2_rn(a.x, a.y);
    h[1] = __floats2half2_rn(a.z, a.w);
    h[2] = __floats2half2_rn(b.x, b.y);
    h[3] = __floats2half2_rn(b.z, b.w);
    *(uint4*)(dst + off * 8) = *(uint4*)h;
}

// ---------------------------------------------------------------------------
// fp16 GEMM: CTA 128x128, 128 threads, 4 warps (2m x 2n), warp 64x64.
// BK=64, 3-stage cp.async ring. At the legacy-HMMA rate ceiling.
// (round-14 version: non-persistent — persistent variant regressed)
// ---------------------------------------------------------------------------
#define G_ABYTES (128*144)              /* 18432 */
#define G_BBYTES (64*272)               /* 17408 */
#define G_STAGE  (G_ABYTES + G_BBYTES)  /* 35840 */
#define G_SMEM   (3*G_STAGE)            /* 107520 */
#define G_KIT    (EMB/64)               /* 16 */

template<int LDW>
__device__ __forceinline__ void g_fill(
    const __half* __restrict__ A, const __half* __restrict__ W,
    int bm, int bn, uint32_t sbase, int kc, int st)
{
    const int tid = threadIdx.x;
    const uint32_t as = sbase + st*G_STAGE;
    const uint32_t bs = as + G_ABYTES;
#pragma unroll
    for (int it = 0; it < 8; it++) {  // A: 128 rows x 8 segs (128B/row)
        const int u = it*128 + tid;
        const int r = u >> 3, sg = u & 7;
        CPA16(as + r*144 + sg*16, A + (size_t)(bm + r)*EMB + kc + sg*8);
    }
#pragma unroll
    for (int it = 0; it < 8; it++) {  // B: 64 k-rows x 16 segs (256B/row)
        const int u = it*128 + tid;
        const int k = u >> 4, sg = u & 15;
        CPA16(bs + k*272 + sg*16, W + (size_t)(kc + k)*LDW + bn + sg*8);
    }
}

template<int LDW>
__device__ __forceinline__ void g_mainloop(
    const __half* __restrict__ A, const __half* __restrict__ W,
    int bm, int bn, uint32_t sbase, float acc[4][8][4])
{
    const int warp = threadIdx.x >> 5, lane = threadIdx.x & 31;
    const int wm = warp >> 1, wn = warp & 1;
    const int l7 = lane & 7, l8 = (lane >> 3) & 1, l16 = lane >> 4;

#pragma unroll
    for (int mt = 0; mt < 4; mt++)
#pragma unroll
        for (int nt = 0; nt < 8; nt++)
#pragma unroll
            for (int r = 0; r < 4; r++) acc[mt][nt][r] = 0.f;

    g_fill<LDW>(A, W, bm, bn, sbase, 0, 0);   CP_COMMIT();
    g_fill<LDW>(A, W, bm, bn, sbase, 64, 1);  CP_COMMIT();

    int st = 0;
    for (int i = 0; i < G_KIT; i++) {
        if (i == G_KIT - 1) CP_WAIT0(); else CP_WAIT1();
        __syncthreads();
        if (i + 2 < G_KIT) {
            int st2 = st + 2; if (st2 >= 3) st2 -= 3;
            g_fill<LDW>(A, W, bm, bn, sbase, (i+2)*64, st2);
            CP_COMMIT();
        }
        const uint32_t as = sbase + st*G_STAGE;
        const uint32_t bs = as + G_ABYTES;
#pragma unroll
        for (int ks = 0; ks < 4; ks++) {
            uint32_t a[4][4];
#pragma unroll
            for (int mt = 0; mt < 4; mt++) {
                const int row = wm*64 + mt*16 + l7 + l8*8;
                const int col = ks*16 + l16*8;
                LDSM4(a[mt][0], a[mt][1], a[mt][2], a[mt][3],
                      as + row*144 + col*2);
            }
            uint32_t b[8][2];
#pragma unroll
            for (int np = 0; np < 4; np++) {
                const int row = ks*16 + l7 + l16*8;       // k
                const int col = wn*64 + np*16 + l8*8;     // n
                uint32_t r0, r1, r2, r3;
                LDSM4T(r0, r1, r2, r3, bs + row*272 + col*2);
                b[np*2  ][0] = r0; b[np*2  ][1] = r2;
                b[np*2+1][0] = r1; b[np*2+1][1] = r3;
            }
#pragma unroll
            for (int mt = 0; mt < 4; mt++)
#pragma unroll
                for (int nt = 0; nt < 8; nt++)
                    mma16(acc[mt][nt], a[mt], b[nt][0], b[nt][1]);
        }
        if (++st >= 3) st = 0;
    }
}

// ---------------------------------------------------------------------------
// QKV GEMM: g_xh[8192,1024] @ g_wh[1024,3072] + b -> g_q/g_k/g_v (fp16)
// ---------------------------------------------------------------------------
__global__ __launch_bounds__(128, 2) void qkv_gemm_kernel(
    const float* __restrict__ bias)
{
    extern __shared__ char smem[];
    const uint32_t sbase = smem_u32(smem);
    const int bm = blockIdx.y * 128, bn = blockIdx.x * 128;

    float acc[4][8][4];
    g_mainloop<NQKV>(g_xh, g_wh, bm, bn, sbase, acc);

    const int warp = threadIdx.x >> 5, lane = threadIdx.x & 31;
    const int wm = warp >> 1, wn = warp & 1;
    const int g = lane >> 2, t4 = lane & 3;
#pragma unroll
    for (int mt = 0; mt < 4; mt++) {
#pragma unroll
        for (int nt = 0; nt < 8; nt++) {
            const int n0 = bn + wn*64 + nt*8 + 2*t4;
            const int sect = n0 >> 10;
            const int e = n0 & (EMB-1);
            const int h = e >> 6, d = e & 63;
            __half* dst = (sect == 0) ? g_q : (sect == 1) ? g_k : g_v;
            const float bx = bias[n0], by = bias[n0+1];
#pragma unroll
            for (int half = 0; half < 2; half++) {
                const int m = bm + wm*64 + mt*16 + g + half*8;
                const int bb = m >> 11, s = m & (SEQ-1);
                __half2 v = __floats2half2_rn(acc[mt][nt][half*2+0] + bx,
                                              acc[mt][nt][half*2+1] + by);
                *(__half2*)&dst[(((size_t)(bb*NH + h))*SEQ + s)*HD + d] = v;
            }
        }
    }
}

// ---------------------------------------------------------------------------
// Proj GEMM: g_y[8192,1024] @ g_wph[1024,1024] + b -> out (fp32)
// ---------------------------------------------------------------------------
__global__ __launch_bounds__(128, 2) void proj_gemm_kernel(
    const float* __restrict__ bias, float* __restrict__ out)
{
    extern __shared__ char smem[];
    const uint32_t sbase = smem_u32(smem);
    const int bm = blockIdx.y * 128, bn = blockIdx.x * 128;

    float acc[4][8][4];
    g_mainloop<EMB>(g_y, g_wph, bm, bn, sbase, acc);

    const int warp = threadIdx.x >> 5, lane = threadIdx.x & 31;
    const int wm = warp >> 1, wn = warp & 1;
    const int g = lane >> 2, t4 = lane & 3;
#pragma unroll
    for (int mt = 0; mt < 4; mt++) {
#pragma unroll
        for (int nt = 0; nt < 8; nt++) {
            const int n0 = bn + wn*64 + nt*8 + 2*t4;
            const float bx = bias[n0], by = bias[n0+1];
#pragma unroll
            for (int half = 0; half < 2; half++) {
                const int m = bm + wm*64 + mt*16 + g + half*8;
                float2 v;
                v.x = acc[mt][nt][half*2+0] + bx;
                v.y = acc[mt][nt][half*2+1] + by;
                *(float2*)&out[(size_t)m*EMB + n0] = v;
            }
        }
    }
}

// ---------------------------------------------------------------------------
// Flash attention: 128-thread CTA over 64 q-rows (4 warps x 16 rows),
// KV tiles of 64, 3-stage cp.async KV ring, max-free softmax, register
// P-reuse. LONGEST-FIRST scheduling: qt = 31 - blockIdx.x so the heaviest
// CTAs (work ~ qt+1) dispatch in the first wave and short CTAs pack the tail.
// smem (halfs): SQ[64][72] @0; stage s: K @4608+s*9216, V = K+4608.
// Total 64512 B -> 3 CTAs/SM.
// ---------------------------------------------------------------------------
#define AQ_OFF  0
#define AKV(s)  (4608 + (s)*9216)
#define ATTN_SMEM_BYTES (32256*2)       /* 64512 */

__global__ __launch_bounds__(128, 3) void attn_kernel()
{
    extern __shared__ __half smh[];
    const uint32_t su = smem_u32(smh);

    const int tid = threadIdx.x;
    const int w = tid >> 5, lane = tid & 31;
    const int g = lane >> 2, t4 = lane & 3;
    const int l7 = lane & 7, l8 = (lane >> 3) & 1, l16 = lane >> 4;
    const int qt = (SEQ/64 - 1) - blockIdx.x;   // longest-first (LPT)
    const int bh = blockIdx.y;
    const int q0 = qt * 64;
    const int qrow = w * 16;
    const size_t base = (size_t)bh * SEQ * HD;
    const __half* Qg = g_q + base;
    const __half* Kg = g_k + base;
    const __half* Vg = g_v + base;
    const int ntiles = qt + 1;

    // Q fill (raw copy): 64 rows x 8 segs = 512 units
#pragma unroll
    for (int it = 0; it < 4; it++) {
        const int u = it*128 + tid;
        const int r = u >> 3, sg = u & 7;
        CPA16(su + (AQ_OFF + r*72)*2 + sg*16, Qg + (size_t)(q0 + r)*HD + sg*8);
    }
    // KV tile 0 into stage 0 (same group as Q)
    {
        const uint32_t ak = su + AKV(0)*2, av = ak + 4608*2;
#pragma unroll
        for (int it = 0; it < 4; it++) {
            const int u = it*128 + tid;
            const int r = u >> 3, sg = u & 7;
            CPA16(ak + r*144 + sg*16, Kg + (size_t)r*HD + sg*8);
            CPA16(av + r*144 + sg*16, Vg + (size_t)r*HD + sg*8);
        }
    }
    CP_COMMIT();
    if (ntiles > 1) {
        const uint32_t ak = su + AKV(1)*2, av = ak + 4608*2;
#pragma unroll
        for (int it = 0; it < 4; it++) {
            const int u = it*128 + tid;
            const int r = u >> 3, sg = u & 7;
            CPA16(ak + r*144 + sg*16, Kg + (size_t)(64 + r)*HD + sg*8);
            CPA16(av + r*144 + sg*16, Vg + (size_t)(64 + r)*HD + sg*8);
        }
        CP_COMMIT();
    }

    float l0 = 0.f, l1 = 0.f;
    float oacc[8][4];
#pragma unroll
    for (int nt = 0; nt < 8; nt++)
#pragma unroll
        for (int r = 0; r < 4; r++) oacc[nt][r] = 0.f;

    const float qs2 = 0.125f * LOG2E;
    int st = 0;
    for (int tk = 0; tk < ntiles; tk++) {
        if (tk == ntiles - 1) CP_WAIT0(); else CP_WAIT1();
        __syncthreads();
        if (tk + 2 < ntiles) {
            int st2 = st + 2; if (st2 >= 3) st2 -= 3;
            const uint32_t ak = su + AKV(st2)*2, av = ak + 4608*2;
#pragma unroll
            for (int it = 0; it < 4; it++) {
                const int u = it*128 + tid;
                const int r = u >> 3, sg = u & 7;
                CPA16(ak + r*144 + sg*16, Kg + (size_t)((tk+2)*64 + r)*HD + sg*8);
                CPA16(av + r*144 + sg*16, Vg + (size_t)((tk+2)*64 + r)*HD + sg*8);
            }
            CP_COMMIT();
        }
        const uint32_t ak = su + AKV(st)*2, av = ak + 4608*2;

        // S = Q K^T
        float sacc[8][4];
#pragma unroll
        for (int nt = 0; nt < 8; nt++)
#pragma unroll
            for (int r = 0; r < 4; r++) sacc[nt][r] = 0.f;

#pragma unroll
        for (int ks = 0; ks < 4; ks++) {
            uint32_t a[4];
            {
                const int row = qrow + l7 + l8*8;
                const int col = ks*16 + l16*8;
                LDSM4(a[0], a[1], a[2], a[3], su + (AQ_OFF + row*72 + col)*2);
            }
#pragma unroll
            for (int np = 0; np < 4; np++) {
                const int row = np*16 + l7 + l8*8;
                const int col = ks*16 + l16*8;
                uint32_t r0, r1, r2, r3;
                LDSM4(r0, r1, r2, r3, ak + row*144 + col*2);
                mma16(sacc[np*2],   a, r0, r2);
                mma16(sacc[np*2+1], a, r1, r3);
            }
        }

        const int row0 = q0 + qrow + g;
        const int row1 = row0 + 8;
        if (tk == ntiles - 1) {    // diagonal tile: causal mask
#pragma unroll
            for (int nt = 0; nt < 8; nt++) {
                const int col = tk*64 + nt*8 + 2*t4;
                if (col   > row0) sacc[nt][0] = NEG_BIG;
                if (col+1 > row0) sacc[nt][1] = NEG_BIG;
                if (col   > row1) sacc[nt][2] = NEG_BIG;
                if (col+1 > row1) sacc[nt][3] = NEG_BIG;
            }
        }

        // max-free softmax: p = ex2(s * qs2)  (masked -> ex2(-big) = 0)
        float s0 = 0.f, s1 = 0.f;
#pragma unroll
        for (int nt = 0; nt < 8; nt++) {
            sacc[nt][0] = ex2(sacc[nt][0] * qs2);
            sacc[nt][1] = ex2(sacc[nt][1] * qs2);
            sacc[nt][2] = ex2(sacc[nt][2] * qs2);
            sacc[nt][3] = ex2(sacc[nt][3] * qs2);
            s0 += sacc[nt][0] + sacc[nt][1];
            s1 += sacc[nt][2] + sacc[nt][3];
        }
        s0 += __shfl_xor_sync(0xffffffffu, s0, 1);
        s0 += __shfl_xor_sync(0xffffffffu, s0, 2);
        s1 += __shfl_xor_sync(0xffffffffu, s1, 1);
        s1 += __shfl_xor_sync(0xffffffffu, s1, 2);
        l0 += s0;
        l1 += s1;

        // O += P V  — A-fragment built directly from the S C-fragment
#pragma unroll
        for (int kk = 0; kk < 4; kk++) {
            uint32_t a[4];
            a[0] = packh2(sacc[2*kk  ][0], sacc[2*kk  ][1]);
            a[1] = packh2(sacc[2*kk  ][2], sacc[2*kk  ][3]);
            a[2] = packh2(sacc[2*kk+1][0], sacc[2*kk+1][1]);
            a[3] = packh2(sacc[2*kk+1][2], sacc[2*kk+1][3]);
#pragma unroll
            for (int dp = 0; dp < 4; dp++) {
                const int row = kk*16 + l7 + l16*8;
                const int col = dp*16 + l8*8;
                uint32_t r0, r1, r2, r3;
                LDSM4T(r0, r1, r2, r3, av + row*144 + col*2);
                mma16(oacc[dp*2],   a, r0, r2);
                mma16(oacc[dp*2+1], a, r1, r3);
            }
        }
        if (++st >= 3) st = 0;
    }

    // normalize + write merged-head layout [B*S, E] fp16
    const int b = bh >> 4, h = bh & 15;
    const float i0 = 1.0f / l0, i1 = 1.0f / l1;
    const int r0 = q0 + qrow + g;
#pragma unroll
    for (int nt = 0; nt < 8; nt++) {
        const int col = h*64 + nt*8 + 2*t4;
        *(__half2*)&g_y[((size_t)(b*SEQ + r0))*EMB + col] =
            __floats2half2_rn(oacc[nt][0]*i0, oacc[nt][1]*i0);
        *(__half2*)&g_y[((size_t)(b*SEQ + r0 + 8))*EMB + col] =
            __floats2half2_rn(oacc[nt][2]*i1, oacc[nt][3]*i1);
    }
}

// ---------------------------------------------------------------------------
extern "C" void kernel_launch(void* const* d_in, const int* in_sizes, int n_in,
                              void* d_out, int out_size)
{
    const float* x      = (const float*)d_in[0];
    const float* w_qkv  = (const float*)d_in[1];
    const float* b_qkv  = (const float*)d_in[2];
    const float* w_proj = (const float*)d_in[3];
    const float* b_proj = (const float*)d_in[4];
    float* out = (float*)d_out;

    cudaFuncSetAttribute(qkv_gemm_kernel,
                         cudaFuncAttributeMaxDynamicSharedMemorySize, G_SMEM);
    cudaFuncSetAttribute(proj_gemm_kernel,
                         cudaFuncAttributeMaxDynamicSharedMemorySize, G_SMEM);
    cudaFuncSetAttribute(attn_kernel,
                         cudaFuncAttributeMaxDynamicSharedMemorySize, ATTN_SMEM_BYTES);

    const int ncvt = N8_X + N8_WQ + N8_WP;
    cvt_all_kernel<<<(ncvt + 255)/256, 256>>>(x, w_qkv, w_proj);

    qkv_gemm_kernel<<<dim3(NQKV/128, MTOT/128), 128, G_SMEM>>>(b_qkv);
    attn_kernel<<<dim3(SEQ/64, BSZ*NH), 128, ATTN_SMEM_BYTES>>>();
    proj_gemm_kernel<<<dim3(EMB/128, MTOT/128), 128, G_SMEM>>>(b_proj, out);
}